// round 6
// baseline (speedup 1.0000x reference)
#include <cuda_runtime.h>
#include <cuda_fp16.h>
#include <math.h>

#define MAXN 100000
#define MAXE 1000000
#define F 64
#define NLAYER 4
#define ALPHA 0.1f
#define SA 68

// ---------------- device scratch (no cudaMalloc allowed) ----------------
__device__ int   g_is64;
__device__ int   g_cnt[MAXN];
__device__ int   g_ptr[MAXN + 1];
__device__ int   g_cur[MAXN];
__device__ int   g_rowv[MAXE];
__device__ int   g_colv[MAXE];
__device__ int   g_srcv[MAXE];
__device__ int   g_bsum[128];
__device__ float g_dis[MAXN];
__device__ float g_bufA[MAXN * F];
__device__ float g_bufB[MAXN * F];
__device__ float g_t16[MAXN * 16];
__device__ float g_y[MAXN];

// ---------------- init: detect dtype + zero counters ----------------
__global__ void k_init(const int* ei32, int n) {
    int i = blockIdx.x * blockDim.x + threadIdx.x;
    if (i < n) g_cnt[i] = 0;
    if (i == 0) {
        int odd_or = 0;
        for (int k = 1; k < 256; k += 2) odd_or |= ei32[k];
        g_is64 = (odd_or == 0) ? 1 : 0;
    }
}

// convert edges to int32 + in-degree histogram on col
__global__ void k_convert_count(const void* ei, int E) {
    int e = blockIdx.x * blockDim.x + threadIdx.x;
    if (e >= E) return;
    int r, c;
    if (g_is64) {
        const long long* p = (const long long*)ei;
        r = (int)p[e];
        c = (int)p[e + E];
    } else {
        const int* p = (const int*)ei;
        r = p[e];
        c = p[e + E];
    }
    g_rowv[e] = r;
    g_colv[e] = c;
    atomicAdd(&g_cnt[c], 1);
}

// ---------------- scan pass 1: per-block inclusive scan + dis ----------------
__global__ void k_scan1(int n) {
    __shared__ int s[1024];
    int i = blockIdx.x * 1024 + threadIdx.x;
    int v = (i < n) ? g_cnt[i] : 0;
    if (i < n) g_dis[i] = rsqrtf((float)v + 1.0f);  // +1 self loop
    s[threadIdx.x] = v;
    __syncthreads();
    for (int off = 1; off < 1024; off <<= 1) {
        int t = (threadIdx.x >= off) ? s[threadIdx.x - off] : 0;
        __syncthreads();
        s[threadIdx.x] += t;
        __syncthreads();
    }
    if (i < n) g_ptr[i] = s[threadIdx.x] - v;  // exclusive within block
    if (threadIdx.x == 1023) g_bsum[blockIdx.x] = s[1023];
}

// ---------------- scan pass 2 (block-offset fixup fused in) ----------------
__global__ void k_scan23(int n, int E) {
    __shared__ int sb[128];
    __shared__ int base;
    int tid = threadIdx.x;
    if (tid < 128) sb[tid] = (tid < (int)gridDim.x) ? g_bsum[tid] : 0;
    __syncthreads();
    if (tid == 0) {
        int r = 0;
        for (int b = 0; b < (int)blockIdx.x; b++) r += sb[b];
        base = r;
    }
    __syncthreads();
    int i = blockIdx.x * 1024 + tid;
    if (i < n) {
        int p = g_ptr[i] + base;
        g_ptr[i] = p;
        g_cur[i] = p;
    }
    if (i == 0) g_ptr[n] = E;
}

// ---------------- scatter edges into CSR + prescale x by dis ----------------
__global__ void k_scatter_scale(const float* __restrict__ x, int E, int n) {
    int i = blockIdx.x * blockDim.x + threadIdx.x;
    if (i < E) {
        int c = g_colv[i];
        int pos = atomicAdd(&g_cur[c], 1);
        g_srcv[pos] = g_rowv[i];
    } else {
        int j = i - E;  // float4 index into xs
        if (j < n * 16) {
            int node = j >> 4, q = j & 15;
            float4 v = ((const float4*)x)[node * 16 + q];
            float d = g_dis[node];
            v.x *= d; v.y *= d; v.z *= d; v.w *= d;
            ((float4*)g_bufA)[node * 16 + q] = v;  // xs lives in bufA
        }
    }
}

// ============ fused layer: propagate + mix + GEMM64x64 + relu (+prescale) ====
// As[rr] = 0.9*d*(sum_src hs[src] + hs[self]) + 0.1*x0 ; Out = relu(As@W)[*dis]
__device__ __forceinline__ void gather_tile(const float* __restrict__ hs,
                                            const float* __restrict__ x0,
                                            float* As, int r0, int n,
                                            int wid, int lane) {
    const float2* H = (const float2*)hs;
    const float2* X = (const float2*)x0;
#pragma unroll 1
    for (int i = 0; i < 8; i++) {
        int rr = wid * 8 + i;
        int node = r0 + rr;
        float2 o = make_float2(0.f, 0.f);
        if (node < n) {
            int beg = g_ptr[node], end = g_ptr[node + 1];
            float sx = 0.f, sy = 0.f;
            int e = beg;
            for (; e + 4 <= end; e += 4) {
                int s0 = g_srcv[e], s1 = g_srcv[e + 1];
                int s2 = g_srcv[e + 2], s3 = g_srcv[e + 3];
                float2 v0 = H[s0 * 32 + lane];
                float2 v1 = H[s1 * 32 + lane];
                float2 v2 = H[s2 * 32 + lane];
                float2 v3 = H[s3 * 32 + lane];
                sx += v0.x + v1.x + v2.x + v3.x;
                sy += v0.y + v1.y + v2.y + v3.y;
            }
            for (; e < end; e++) {
                float2 v = H[g_srcv[e] * 32 + lane];
                sx += v.x; sy += v.y;
            }
            float d = g_dis[node];
            float2 hself = H[node * 32 + lane];
            float2 xv = X[node * 32 + lane];
            o.x = (1.0f - ALPHA) * d * (sx + hself.x) + ALPHA * xv.x;
            o.y = (1.0f - ALPHA) * d * (sy + hself.y) + ALPHA * xv.y;
        }
        *(float2*)&As[rr * SA + lane * 2] = o;
    }
}

__global__ void __launch_bounds__(256) k_layer(
    const float* __restrict__ hs, const float* __restrict__ x0,
    const float* __restrict__ W, float* __restrict__ Out, int n, int doscale) {
    __shared__ float Ws[64 * SA];
    __shared__ float As[64 * SA];
    int tid = threadIdx.x;
    int r0 = blockIdx.x * 64;
    const float4* W4 = (const float4*)W;
    for (int i = tid; i < 1024; i += 256) {
        int k = i >> 4, q = i & 15;
        *(float4*)&Ws[k * SA + q * 4] = W4[i];
    }
    gather_tile(hs, x0, As, r0, n, tid >> 5, tid & 31);
    __syncthreads();

    int tx = tid & 15, ty = tid >> 4;
    float acc[4][4] = {};
#pragma unroll 8
    for (int k = 0; k < 64; k++) {
        float4 w4 = *(const float4*)&Ws[k * SA + tx * 4];
        float a0 = As[(ty * 4 + 0) * SA + k];
        float a1 = As[(ty * 4 + 1) * SA + k];
        float a2 = As[(ty * 4 + 2) * SA + k];
        float a3 = As[(ty * 4 + 3) * SA + k];
        acc[0][0] += a0 * w4.x; acc[0][1] += a0 * w4.y; acc[0][2] += a0 * w4.z; acc[0][3] += a0 * w4.w;
        acc[1][0] += a1 * w4.x; acc[1][1] += a1 * w4.y; acc[1][2] += a1 * w4.z; acc[1][3] += a1 * w4.w;
        acc[2][0] += a2 * w4.x; acc[2][1] += a2 * w4.y; acc[2][2] += a2 * w4.z; acc[2][3] += a2 * w4.w;
        acc[3][0] += a3 * w4.x; acc[3][1] += a3 * w4.y; acc[3][2] += a3 * w4.z; acc[3][3] += a3 * w4.w;
    }
#pragma unroll
    for (int i = 0; i < 4; i++) {
        int r = r0 + ty * 4 + i;
        if (r < n) {
            float sc = doscale ? g_dis[r] : 1.0f;
            float4 o;
            o.x = fmaxf(acc[i][0], 0.f) * sc;
            o.y = fmaxf(acc[i][1], 0.f) * sc;
            o.z = fmaxf(acc[i][2], 0.f) * sc;
            o.w = fmaxf(acc[i][3], 0.f) * sc;
            *(float4*)&Out[r * F + tx * 4] = o;
        }
    }
}

// ===== last layer: propagate + mix + GEMM64x64 + relu + GEMM64x16*dis ========
__global__ void __launch_bounds__(256) k_layer_last(
    const float* __restrict__ hs, const float* __restrict__ x0,
    const float* __restrict__ W, const float* __restrict__ W1,
    float* __restrict__ T16, int n) {
    __shared__ float Ws[64 * SA];
    __shared__ float As[64 * SA];
    __shared__ float W1s[64 * 16];
    int tid = threadIdx.x;
    int r0 = blockIdx.x * 64;
    const float4* W4 = (const float4*)W;
    for (int i = tid; i < 1024; i += 256) {
        int k = i >> 4, q = i & 15;
        *(float4*)&Ws[k * SA + q * 4] = W4[i];
    }
    for (int i = tid; i < 1024; i += 256) W1s[i] = W1[i];
    gather_tile(hs, x0, As, r0, n, tid >> 5, tid & 31);
    __syncthreads();

    int tx = tid & 15, ty = tid >> 4;
    float acc[4][4] = {};
#pragma unroll 8
    for (int k = 0; k < 64; k++) {
        float4 w4 = *(const float4*)&Ws[k * SA + tx * 4];
        float a0 = As[(ty * 4 + 0) * SA + k];
        float a1 = As[(ty * 4 + 1) * SA + k];
        float a2 = As[(ty * 4 + 2) * SA + k];
        float a3 = As[(ty * 4 + 3) * SA + k];
        acc[0][0] += a0 * w4.x; acc[0][1] += a0 * w4.y; acc[0][2] += a0 * w4.z; acc[0][3] += a0 * w4.w;
        acc[1][0] += a1 * w4.x; acc[1][1] += a1 * w4.y; acc[1][2] += a1 * w4.z; acc[1][3] += a1 * w4.w;
        acc[2][0] += a2 * w4.x; acc[2][1] += a2 * w4.y; acc[2][2] += a2 * w4.z; acc[2][3] += a2 * w4.w;
        acc[3][0] += a3 * w4.x; acc[3][1] += a3 * w4.y; acc[3][2] += a3 * w4.z; acc[3][3] += a3 * w4.w;
    }
    __syncthreads();  // As re-use: write relu(h) into Ws region (Ws done)
#pragma unroll
    for (int i = 0; i < 4; i++) {
        int rr = ty * 4 + i;
        Ws[rr * SA + tx * 4 + 0] = fmaxf(acc[i][0], 0.f);
        Ws[rr * SA + tx * 4 + 1] = fmaxf(acc[i][1], 0.f);
        Ws[rr * SA + tx * 4 + 2] = fmaxf(acc[i][2], 0.f);
        Ws[rr * SA + tx * 4 + 3] = fmaxf(acc[i][3], 0.f);
    }
    __syncthreads();
    // h(64x64 in Ws) @ W1(64x16) -> T16, prescaled by dis
    for (int idx = tid; idx < 1024; idx += 256) {
        int rr = idx >> 4, j = idx & 15;
        int r = r0 + rr;
        if (r < n) {
            float a = 0.f;
#pragma unroll 8
            for (int k = 0; k < 64; k++) a += Ws[rr * SA + k] * W1s[k * 16 + j];
            T16[r * 16 + j] = a * g_dis[r];
        }
    }
}

// ---------------- propagate 16-wide + b1, fused 16->1 GEMV, prescale ----------
__global__ void k_prop16_gemv(const float* __restrict__ ts, const float* __restrict__ b1,
                              const float* __restrict__ w2, float* __restrict__ ys, int n) {
    int t = threadIdx.x;
    int node = blockIdx.x * 16 + (t >> 4);
    int f = t & 15;
    bool ok = node < n;
    int beg = 0, end = 0;
    if (ok) { beg = g_ptr[node]; end = g_ptr[node + 1]; }
    float s = 0.f;
    int e = beg;
    for (; e + 4 <= end; e += 4) {
        int s0 = g_srcv[e], s1 = g_srcv[e + 1], s2 = g_srcv[e + 2], s3 = g_srcv[e + 3];
        s += ts[s0 * 16 + f] + ts[s1 * 16 + f] + ts[s2 * 16 + f] + ts[s3 * 16 + f];
    }
    for (; e < end; e++) s += ts[g_srcv[e] * 16 + f];
    float d = ok ? g_dis[node] : 0.f;
    float self = ok ? ts[node * 16 + f] : 0.f;
    float val = d * (s + self) + b1[f];
    float prod = val * w2[f];
    prod += __shfl_xor_sync(0xffffffffu, prod, 8);
    prod += __shfl_xor_sync(0xffffffffu, prod, 4);
    prod += __shfl_xor_sync(0xffffffffu, prod, 2);
    prod += __shfl_xor_sync(0xffffffffu, prod, 1);
    if (ok && f == 0) ys[node] = d * prod;
}

// ---------------- scalar propagate + b2 + sigmoid ----------------
__global__ void k_prop1_sig(const float* __restrict__ ys, const float* __restrict__ b2,
                            float* __restrict__ out, int n) {
    int node = blockIdx.x * blockDim.x + threadIdx.x;
    if (node >= n) return;
    int beg = g_ptr[node], end = g_ptr[node + 1];
    float s = 0.f;
    int e = beg;
    for (; e + 4 <= end; e += 4) {
        int s0 = g_srcv[e], s1 = g_srcv[e + 1], s2 = g_srcv[e + 2], s3 = g_srcv[e + 3];
        s += ys[s0] + ys[s1] + ys[s2] + ys[s3];
    }
    for (; e < end; e++) s += ys[g_srcv[e]];
    float d = g_dis[node];
    float v = d * (s + ys[node]) + b2[0];
    out[node] = 1.0f / (1.0f + expf(-v));
}

// ---------------- launch ----------------
extern "C" void kernel_launch(void* const* d_in, const int* in_sizes, int n_in,
                              void* d_out, int out_size) {
    const float* x  = (const float*)d_in[0];
    const void*  ei = d_in[1];
    const float* gw = (const float*)d_in[2];  // (4,64,64)
    const float* w1 = (const float*)d_in[3];  // (64,16)
    const float* b1 = (const float*)d_in[4];
    const float* w2 = (const float*)d_in[5];  // (16,1)
    const float* b2 = (const float*)d_in[6];
    float* out = (float*)d_out;

    const int N = in_sizes[0] / F;
    const int E = in_sizes[1] / 2;

    float* bufA; cudaGetSymbolAddress((void**)&bufA, g_bufA);
    float* bufB; cudaGetSymbolAddress((void**)&bufB, g_bufB);
    float* t16;  cudaGetSymbolAddress((void**)&t16,  g_t16);
    float* yv;   cudaGetSymbolAddress((void**)&yv,   g_y);

    const int T = 256;
    int nb_n = (N + T - 1) / T;
    int nb_e = (E + T - 1) / T;
    int nb_scan = (N + 1023) / 1024;
    int nb_ss = (E + N * 16 + T - 1) / T;
    int nb_g = (N + 63) / 64;
    int nb_g16 = (N + 15) / 16;

    // 0..4: graph norm + CSR build (+ x prescale)
    k_init<<<nb_n, T>>>((const int*)ei, N);
    k_convert_count<<<nb_e, T>>>(ei, E);
    k_scan1<<<nb_scan, 1024>>>(N);
    k_scan23<<<nb_scan, 1024>>>(N, E);
    k_scatter_scale<<<nb_ss, T>>>(x, E, N);

    // 5..8: GCN2Conv stack, fully fused per layer (xs starts in bufA)
    k_layer<<<nb_g, 256>>>(bufA, x, gw + 0 * 4096, bufB, N, 1);
    k_layer<<<nb_g, 256>>>(bufB, x, gw + 1 * 4096, bufA, N, 1);
    k_layer<<<nb_g, 256>>>(bufA, x, gw + 2 * 4096, bufB, N, 1);
    k_layer_last<<<nb_g, 256>>>(bufB, x, gw + 3 * 4096, w1, t16, N);

    // tail
    k_prop16_gemv<<<nb_g16, 256>>>(t16, b1, w2, yv, N);
    k_prop1_sig<<<nb_n, T>>>(yv, b2, out, N);
}

// round 10
// speedup vs baseline: 1.1174x; 1.1174x over previous
#include <cuda_runtime.h>
#include <cuda_fp16.h>
#include <math.h>

#define MAXN 100000
#define MAXE 1000000
#define F 64
#define NLAYER 4
#define ALPHA 0.1f
#define SA 68

// ---------------- device scratch (no cudaMalloc allowed) ----------------
__device__ int    g_is64;
__device__ int    g_cnt[MAXN];
__device__ int    g_ptr[MAXN + 1];
__device__ int    g_cur[MAXN];
__device__ int    g_rowv[MAXE];
__device__ int    g_colv[MAXE];
__device__ int    g_srcv[MAXE];
__device__ int    g_bsum[128];
__device__ float  g_dis[MAXN];
__device__ __half g_hA[MAXN * F];   // fp16 node features (prescaled by dis)
__device__ __half g_hB[MAXN * F];
__device__ float  g_t16[MAXN * 16];
__device__ float  g_y[MAXN];

// ---------------- init: detect dtype + zero counters ----------------
__global__ void k_init(const int* ei32, int n) {
    int i = blockIdx.x * blockDim.x + threadIdx.x;
    if (i < n) g_cnt[i] = 0;
    if (i == 0) {
        int odd_or = 0;
        for (int k = 1; k < 256; k += 2) odd_or |= ei32[k];
        g_is64 = (odd_or == 0) ? 1 : 0;
    }
}

// convert edges to int32 + in-degree histogram on col
__global__ void k_convert_count(const void* ei, int E) {
    int e = blockIdx.x * blockDim.x + threadIdx.x;
    if (e >= E) return;
    int r, c;
    if (g_is64) {
        const long long* p = (const long long*)ei;
        r = (int)p[e];
        c = (int)p[e + E];
    } else {
        const int* p = (const int*)ei;
        r = p[e];
        c = p[e + E];
    }
    g_rowv[e] = r;
    g_colv[e] = c;
    atomicAdd(&g_cnt[c], 1);
}

// ---------------- scan pass 1: per-block inclusive scan + dis ----------------
__global__ void k_scan1(int n) {
    __shared__ int s[1024];
    int i = blockIdx.x * 1024 + threadIdx.x;
    int v = (i < n) ? g_cnt[i] : 0;
    if (i < n) g_dis[i] = rsqrtf((float)v + 1.0f);  // +1 self loop
    s[threadIdx.x] = v;
    __syncthreads();
    for (int off = 1; off < 1024; off <<= 1) {
        int t = (threadIdx.x >= off) ? s[threadIdx.x - off] : 0;
        __syncthreads();
        s[threadIdx.x] += t;
        __syncthreads();
    }
    if (i < n) g_ptr[i] = s[threadIdx.x] - v;  // exclusive within block
    if (threadIdx.x == 1023) g_bsum[blockIdx.x] = s[1023];
}

// ---------------- scan pass 2 (block-offset fixup fused in) ----------------
__global__ void k_scan23(int n, int E) {
    __shared__ int sb[128];
    __shared__ int base;
    int tid = threadIdx.x;
    if (tid < 128) sb[tid] = (tid < (int)gridDim.x) ? g_bsum[tid] : 0;
    __syncthreads();
    if (tid == 0) {
        int r = 0;
        for (int b = 0; b < (int)blockIdx.x; b++) r += sb[b];
        base = r;
    }
    __syncthreads();
    int i = blockIdx.x * 1024 + tid;
    if (i < n) {
        int p = g_ptr[i] + base;
        g_ptr[i] = p;
        g_cur[i] = p;
    }
    if (i == 0) g_ptr[n] = E;
}

// ---------- scatter edges into CSR + prescale x by dis -> fp16 in g_hA ------
__global__ void k_scatter_scale(const float* __restrict__ x, int E, int n) {
    int i = blockIdx.x * blockDim.x + threadIdx.x;
    if (i < E) {
        int c = g_colv[i];
        int pos = atomicAdd(&g_cur[c], 1);
        g_srcv[pos] = g_rowv[i];
    } else {
        int j = i - E;  // float4 index
        if (j < n * 16) {
            int node = j >> 4;
            float4 v = ((const float4*)x)[j];
            float d = g_dis[node];
            __half2 h0 = __floats2half2_rn(v.x * d, v.y * d);
            __half2 h1 = __floats2half2_rn(v.z * d, v.w * d);
            ((__half2*)g_hA)[j * 2 + 0] = h0;
            ((__half2*)g_hA)[j * 2 + 1] = h1;
        }
    }
}

// ============ fused layer: propagate + mix + GEMM64x64 + relu + prescale ====
// As[rr] = 0.9*d*(sum_src hs[src] + hs[self]) + 0.1*x0 ; Out = half(relu(As@W)*dis)
__device__ __forceinline__ void gather_tile(const __half2* __restrict__ H,
                                            const float2* __restrict__ X,
                                            float* As, int r0, int n,
                                            int wid, int lane) {
#pragma unroll 1
    for (int i = 0; i < 8; i++) {
        int rr = wid * 8 + i;
        int node = r0 + rr;
        float2 o = make_float2(0.f, 0.f);
        if (node < n) {
            int beg = g_ptr[node], end = g_ptr[node + 1];
            float sx = 0.f, sy = 0.f;
            int e = beg;
            for (; e + 4 <= end; e += 4) {
                int s0 = g_srcv[e], s1 = g_srcv[e + 1];
                int s2 = g_srcv[e + 2], s3 = g_srcv[e + 3];
                float2 v0 = __half22float2(H[s0 * 32 + lane]);
                float2 v1 = __half22float2(H[s1 * 32 + lane]);
                float2 v2 = __half22float2(H[s2 * 32 + lane]);
                float2 v3 = __half22float2(H[s3 * 32 + lane]);
                sx += v0.x + v1.x + v2.x + v3.x;
                sy += v0.y + v1.y + v2.y + v3.y;
            }
            for (; e < end; e++) {
                float2 v = __half22float2(H[g_srcv[e] * 32 + lane]);
                sx += v.x; sy += v.y;
            }
            float d = g_dis[node];
            float2 hself = __half22float2(H[node * 32 + lane]);
            float2 xv = X[node * 32 + lane];
            o.x = (1.0f - ALPHA) * d * (sx + hself.x) + ALPHA * xv.x;
            o.y = (1.0f - ALPHA) * d * (sy + hself.y) + ALPHA * xv.y;
        }
        *(float2*)&As[rr * SA + lane * 2] = o;
    }
}

__global__ void __launch_bounds__(256) k_layer(
    const __half2* __restrict__ hs, const float* __restrict__ x0,
    const float* __restrict__ W, __half* __restrict__ Out, int n) {
    __shared__ float Ws[64 * SA];
    __shared__ float As[64 * SA];
    int tid = threadIdx.x;
    int r0 = blockIdx.x * 64;
    const float4* W4 = (const float4*)W;
    for (int i = tid; i < 1024; i += 256) {
        int k = i >> 4, q = i & 15;
        *(float4*)&Ws[k * SA + q * 4] = W4[i];
    }
    gather_tile(hs, (const float2*)x0, As, r0, n, tid >> 5, tid & 31);
    __syncthreads();

    int tx = tid & 15, ty = tid >> 4;
    float acc[4][4] = {};
#pragma unroll 8
    for (int k = 0; k < 64; k++) {
        float4 w4 = *(const float4*)&Ws[k * SA + tx * 4];
        float a0 = As[(ty * 4 + 0) * SA + k];
        float a1 = As[(ty * 4 + 1) * SA + k];
        float a2 = As[(ty * 4 + 2) * SA + k];
        float a3 = As[(ty * 4 + 3) * SA + k];
        acc[0][0] += a0 * w4.x; acc[0][1] += a0 * w4.y; acc[0][2] += a0 * w4.z; acc[0][3] += a0 * w4.w;
        acc[1][0] += a1 * w4.x; acc[1][1] += a1 * w4.y; acc[1][2] += a1 * w4.z; acc[1][3] += a1 * w4.w;
        acc[2][0] += a2 * w4.x; acc[2][1] += a2 * w4.y; acc[2][2] += a2 * w4.z; acc[2][3] += a2 * w4.w;
        acc[3][0] += a3 * w4.x; acc[3][1] += a3 * w4.y; acc[3][2] += a3 * w4.z; acc[3][3] += a3 * w4.w;
    }
#pragma unroll
    for (int i = 0; i < 4; i++) {
        int r = r0 + ty * 4 + i;
        if (r < n) {
            float sc = g_dis[r];
            __half2 h0 = __floats2half2_rn(fmaxf(acc[i][0], 0.f) * sc,
                                           fmaxf(acc[i][1], 0.f) * sc);
            __half2 h1 = __floats2half2_rn(fmaxf(acc[i][2], 0.f) * sc,
                                           fmaxf(acc[i][3], 0.f) * sc);
            uint2 pk;
            pk.x = *reinterpret_cast<unsigned int*>(&h0);
            pk.y = *reinterpret_cast<unsigned int*>(&h1);
            *(uint2*)((__half2*)Out + r * 32 + tx * 2) = pk;
        }
    }
}

// ===== last layer: propagate + mix + GEMM64x64 + relu + GEMM64x16*dis ========
__global__ void __launch_bounds__(256) k_layer_last(
    const __half2* __restrict__ hs, const float* __restrict__ x0,
    const float* __restrict__ W, const float* __restrict__ W1,
    float* __restrict__ T16, int n) {
    __shared__ float Ws[64 * SA];
    __shared__ float As[64 * SA];
    __shared__ float W1s[64 * 16];
    int tid = threadIdx.x;
    int r0 = blockIdx.x * 64;
    const float4* W4 = (const float4*)W;
    for (int i = tid; i < 1024; i += 256) {
        int k = i >> 4, q = i & 15;
        *(float4*)&Ws[k * SA + q * 4] = W4[i];
    }
    for (int i = tid; i < 1024; i += 256) W1s[i] = W1[i];
    gather_tile(hs, (const float2*)x0, As, r0, n, tid >> 5, tid & 31);
    __syncthreads();

    int tx = tid & 15, ty = tid >> 4;
    float acc[4][4] = {};
#pragma unroll 8
    for (int k = 0; k < 64; k++) {
        float4 w4 = *(const float4*)&Ws[k * SA + tx * 4];
        float a0 = As[(ty * 4 + 0) * SA + k];
        float a1 = As[(ty * 4 + 1) * SA + k];
        float a2 = As[(ty * 4 + 2) * SA + k];
        float a3 = As[(ty * 4 + 3) * SA + k];
        acc[0][0] += a0 * w4.x; acc[0][1] += a0 * w4.y; acc[0][2] += a0 * w4.z; acc[0][3] += a0 * w4.w;
        acc[1][0] += a1 * w4.x; acc[1][1] += a1 * w4.y; acc[1][2] += a1 * w4.z; acc[1][3] += a1 * w4.w;
        acc[2][0] += a2 * w4.x; acc[2][1] += a2 * w4.y; acc[2][2] += a2 * w4.z; acc[2][3] += a2 * w4.w;
        acc[3][0] += a3 * w4.x; acc[3][1] += a3 * w4.y; acc[3][2] += a3 * w4.z; acc[3][3] += a3 * w4.w;
    }
    __syncthreads();  // reuse Ws region for relu(h)
#pragma unroll
    for (int i = 0; i < 4; i++) {
        int rr = ty * 4 + i;
        Ws[rr * SA + tx * 4 + 0] = fmaxf(acc[i][0], 0.f);
        Ws[rr * SA + tx * 4 + 1] = fmaxf(acc[i][1], 0.f);
        Ws[rr * SA + tx * 4 + 2] = fmaxf(acc[i][2], 0.f);
        Ws[rr * SA + tx * 4 + 3] = fmaxf(acc[i][3], 0.f);
    }
    __syncthreads();
    // h(64x64 in Ws) @ W1(64x16) -> T16, prescaled by dis
    for (int idx = tid; idx < 1024; idx += 256) {
        int rr = idx >> 4, j = idx & 15;
        int r = r0 + rr;
        if (r < n) {
            float a = 0.f;
#pragma unroll 8
            for (int k = 0; k < 64; k++) a += Ws[rr * SA + k] * W1s[k * 16 + j];
            T16[r * 16 + j] = a * g_dis[r];
        }
    }
}

// ---------------- propagate 16-wide + b1, fused 16->1 GEMV, prescale ----------
__global__ void k_prop16_gemv(const float* __restrict__ ts, const float* __restrict__ b1,
                              const float* __restrict__ w2, float* __restrict__ ys, int n) {
    int t = threadIdx.x;
    int node = blockIdx.x * 16 + (t >> 4);
    int f = t & 15;
    bool ok = node < n;
    int beg = 0, end = 0;
    if (ok) { beg = g_ptr[node]; end = g_ptr[node + 1]; }
    float s = 0.f;
    int e = beg;
    for (; e + 4 <= end; e += 4) {
        int s0 = g_srcv[e], s1 = g_srcv[e + 1], s2 = g_srcv[e + 2], s3 = g_srcv[e + 3];
        s += ts[s0 * 16 + f] + ts[s1 * 16 + f] + ts[s2 * 16 + f] + ts[s3 * 16 + f];
    }
    for (; e < end; e++) s += ts[g_srcv[e] * 16 + f];
    float d = ok ? g_dis[node] : 0.f;
    float self = ok ? ts[node * 16 + f] : 0.f;
    float val = d * (s + self) + b1[f];
    float prod = val * w2[f];
    prod += __shfl_xor_sync(0xffffffffu, prod, 8);
    prod += __shfl_xor_sync(0xffffffffu, prod, 4);
    prod += __shfl_xor_sync(0xffffffffu, prod, 2);
    prod += __shfl_xor_sync(0xffffffffu, prod, 1);
    if (ok && f == 0) ys[node] = d * prod;
}

// ---------------- scalar propagate + b2 + sigmoid ----------------
__global__ void k_prop1_sig(const float* __restrict__ ys, const float* __restrict__ b2,
                            float* __restrict__ out, int n) {
    int node = blockIdx.x * blockDim.x + threadIdx.x;
    if (node >= n) return;
    int beg = g_ptr[node], end = g_ptr[node + 1];
    float s = 0.f;
    int e = beg;
    for (; e + 4 <= end; e += 4) {
        int s0 = g_srcv[e], s1 = g_srcv[e + 1], s2 = g_srcv[e + 2], s3 = g_srcv[e + 3];
        s += ys[s0] + ys[s1] + ys[s2] + ys[s3];
    }
    for (; e < end; e++) s += ys[g_srcv[e]];
    float d = g_dis[node];
    float v = d * (s + ys[node]) + b2[0];
    out[node] = 1.0f / (1.0f + expf(-v));
}

// ---------------- launch ----------------
extern "C" void kernel_launch(void* const* d_in, const int* in_sizes, int n_in,
                              void* d_out, int out_size) {
    const float* x  = (const float*)d_in[0];
    const void*  ei = d_in[1];
    const float* gw = (const float*)d_in[2];  // (4,64,64)
    const float* w1 = (const float*)d_in[3];  // (64,16)
    const float* b1 = (const float*)d_in[4];
    const float* w2 = (const float*)d_in[5];  // (16,1)
    const float* b2 = (const float*)d_in[6];
    float* out = (float*)d_out;

    const int N = in_sizes[0] / F;
    const int E = in_sizes[1] / 2;

    __half* hA; cudaGetSymbolAddress((void**)&hA, g_hA);
    __half* hB; cudaGetSymbolAddress((void**)&hB, g_hB);
    float* t16; cudaGetSymbolAddress((void**)&t16, g_t16);
    float* yv;  cudaGetSymbolAddress((void**)&yv,  g_y);

    const int T = 256;
    int nb_n = (N + T - 1) / T;
    int nb_e = (E + T - 1) / T;
    int nb_scan = (N + 1023) / 1024;
    int nb_ss = (E + N * 16 + T - 1) / T;
    int nb_g = (N + 63) / 64;
    int nb_g16 = (N + 15) / 16;

    // graph norm + CSR build (+ fp16 x prescale into hA)
    k_init<<<nb_n, T>>>((const int*)ei, N);
    k_convert_count<<<nb_e, T>>>(ei, E);
    k_scan1<<<nb_scan, 1024>>>(N);
    k_scan23<<<nb_scan, 1024>>>(N, E);
    k_scatter_scale<<<nb_ss, T>>>(x, E, N);

    // GCN2Conv stack, fused per layer, fp16 inter-layer features
    k_layer<<<nb_g, 256>>>((const __half2*)hA, x, gw + 0 * 4096, hB, N);
    k_layer<<<nb_g, 256>>>((const __half2*)hB, x, gw + 1 * 4096, hA, N);
    k_layer<<<nb_g, 256>>>((const __half2*)hA, x, gw + 2 * 4096, hB, N);
    k_layer_last<<<nb_g, 256>>>((const __half2*)hB, x, gw + 3 * 4096, w1, t16, N);

    // tail
    k_prop16_gemv<<<nb_g16, 256>>>(t16, b1, w2, yv, N);
    k_prop1_sig<<<nb_n, T>>>(yv, b2, out, N);
}